// round 14
// baseline (speedup 1.0000x reference)
#include <cuda_runtime.h>
#include <cuda_fp16.h>

#define N_NODES 100000
#define N_EDGES 3200000
#define HID     32
#define NEG     0.2f
#define ENC_SHIFT 0x007FFFFFu                     // encf(-inf); enc2(-inf) == 0
#define CAP     160                               // CSR slots per node (4 segments)
#define CAP4    40                                // slots per replica segment
#define NODE_BLOCKS  ((N_NODES + 7) / 8)          // 12500 (transform part of k_p1)
#define EDGE4        (N_EDGES / 4)                // 800000
#define EDGE4_BLOCKS ((EDGE4 + 255) / 256)        // 3125
#define GATHER_BLOCKS (N_NODES / 32)              // 3125 (quarter-warp: 32 nodes/block)

// ---- static device scratch ----
__device__ __align__(16) __half g_h16 [N_NODES * HID];  // layer-1 features (fp16)
__device__ __align__(16) __half g_h16b[N_NODES * HID];  // layer-2 features (fp16)
__device__ float    g_as [N_NODES], g_ad [N_NODES];     // layer-1 attention halves
__device__ float    g_as2[N_NODES], g_ad2[N_NODES];     // layer-2 attention halves
__device__ int      g_degK[4 * N_NODES];                // 4-replica degree counters
__device__ int      g_csr[N_NODES * CAP];               // implicit-offset CSR (64MB)
__device__ unsigned g_amax_enc[2];                      // memset-0 == enc2(-inf)

// shifted order-preserving float<->uint encoding: 0 decodes to -inf
__device__ __forceinline__ unsigned enc2(float f) {
    unsigned u = __float_as_uint(f);
    unsigned e = (u & 0x80000000u) ? ~u : (u | 0x80000000u);
    return e - ENC_SHIFT;
}
__device__ __forceinline__ float dec2(unsigned v) {
    unsigned u = v + ENC_SHIFT;
    return (u & 0x80000000u) ? __uint_as_float(u ^ 0x80000000u)
                             : __uint_as_float(~u);
}
__device__ __forceinline__ float lrelu(float x) { return x >= 0.f ? x : NEG * x; }

// ---------------------------------------------------------------------------
// Phase 1 (fused): blocks [0, EDGE4_BLOCKS) = single-pass implicit-offset CSR
// build (scheduled FIRST so the atomic long pole starts immediately); blocks
// beyond = layer-1 transform (h1 = x@W1, a_s/a_d, amax slot 0).
// ---------------------------------------------------------------------------
__global__ void __launch_bounds__(256) k_p1(
    const float* __restrict__ x, const float* __restrict__ W1,
    const float* __restrict__ aw_s, const float* __restrict__ aw_d,
    const int4* __restrict__ src4, const int4* __restrict__ dst4)
{
    if (blockIdx.x < EDGE4_BLOCKS) {
        int i = blockIdx.x * 256 + threadIdx.x;
        if (i < EDGE4) {
            int4 d = dst4[i];
            int4 s = src4[i];
            int r0 = atomicAdd(&g_degK[              d.x], 1);
            int r1 = atomicAdd(&g_degK[    N_NODES + d.y], 1);
            int r2 = atomicAdd(&g_degK[2 * N_NODES + d.z], 1);
            int r3 = atomicAdd(&g_degK[3 * N_NODES + d.w], 1);
            g_csr[d.x * CAP            + r0] = s.x;
            g_csr[d.y * CAP +     CAP4 + r1] = s.y;
            g_csr[d.z * CAP + 2 * CAP4 + r2] = s.z;
            g_csr[d.w * CAP + 3 * CAP4 + r3] = s.w;
        }
        return;
    }

    int wid  = threadIdx.x >> 5;
    int lane = threadIdx.x & 31;
    int node = (blockIdx.x - EDGE4_BLOCKS) * 8 + wid;

    float s = -3.4e38f;
    if (node < N_NODES) {
        float xv = (lane < 3) ? x[node * 3 + lane] : 0.f;
        float x0 = __shfl_sync(0xffffffffu, xv, 0);
        float x1 = __shfl_sync(0xffffffffu, xv, 1);
        float x2 = __shfl_sync(0xffffffffu, xv, 2);

        float h = x0 * W1[lane] + x1 * W1[HID + lane] + x2 * W1[2 * HID + lane];
        g_h16[node * HID + lane] = __float2half(h);

        s = h * aw_s[lane];
        float d = h * aw_d[lane];
#pragma unroll
        for (int o = 16; o; o >>= 1) {
            s += __shfl_xor_sync(0xffffffffu, s, o);
            d += __shfl_xor_sync(0xffffffffu, d, o);
        }
        if (lane == 0) { g_as[node] = s; g_ad[node] = d; }
    }
    __shared__ float warp_s[8];
    if (lane == 0) warp_s[wid] = s;
    __syncthreads();
    if (threadIdx.x == 0) {
        float m = warp_s[0];
#pragma unroll
        for (int i = 1; i < 8; i++) m = fmaxf(m, warp_s[i]);
        atomicMax(&g_amax_enc[0], enc2(m));
    }
}

// ---------------------------------------------------------------------------
// Quarter-warp gather with DOUBLE-BUFFERED stage: one __syncwarp per 8-edge
// chunk. 8 lanes own one node (consecutive nodes per warp for locality); lane
// ql handles features [4ql, 4ql+4) as half4 (uint2). Padded entries carry
// ex = 0; the quarter-uniform e>0 guard skips their LDG + FMAs.
// st: per-warp region float2[2][36] (two buffers, 4 quarters * stride 9).
// ---------------------------------------------------------------------------
__device__ __forceinline__ float4 gather_quarter(
    int node, int ql, int q, float2* __restrict__ st,
    int degmax, int deg, int pre1, int pre2, int pre3,
    const float* __restrict__ asv, const float* __restrict__ adv,
    const __half* __restrict__ hbuf, float Amax)
{
    const float ad = adv[node];
    const float m  = lrelu(Amax + ad);
    const int base = node * CAP;

    float a0 = 0.f, a1 = 0.f, a2 = 0.f, a3 = 0.f, denp = 0.f;

    // prologue: chunk 0 into buffer 0
    {
        int sj = 0; float ex = 0.f;
        if (ql < deg) {
            int idx = ql, slot;
            if      (idx < pre1) slot = idx;
            else if (idx < pre2) slot =     CAP4 + idx - pre1;
            else if (idx < pre3) slot = 2 * CAP4 + idx - pre2;
            else                 slot = 3 * CAP4 + idx - pre3;
            sj = g_csr[base + slot];
            ex = __expf(lrelu(asv[sj] + ad) - m);
        }
        denp += ex;
        st[q * 9 + ql] = make_float2(__int_as_float(sj), ex);
    }
    __syncwarp();

    int p = 0;
    for (int b = 0; b < degmax; b += 8) {
        // prefetch chunk b+8 (registers; loads overlap the consume below)
        int nidx = b + 8 + ql;
        int nsj = 0; float nex = 0.f;
        if (nidx < deg) {
            int slot;
            if      (nidx < pre1) slot = nidx;
            else if (nidx < pre2) slot =     CAP4 + nidx - pre1;
            else if (nidx < pre3) slot = 2 * CAP4 + nidx - pre2;
            else                  slot = 3 * CAP4 + nidx - pre3;
            nsj = g_csr[base + slot];
            nex = __expf(lrelu(asv[nsj] + ad) - m);
        }
        denp += nex;    // chunks beyond deg carry nex = 0, harmless

        // consume chunk b from buffer p
        const float2* cb = st + p * 36 + q * 9;
#pragma unroll
        for (int j = 0; j < 8; j++) {
            float2 pp = cb[j];
            float e   = pp.y;
            if (e > 0.f) {
                int   sE = __float_as_int(pp.x);
                uint2 hv = *reinterpret_cast<const uint2*>(&hbuf[sE * HID + ql * 4]);
                float2 f0 = __half22float2(*reinterpret_cast<half2*>(&hv.x));
                float2 f1 = __half22float2(*reinterpret_cast<half2*>(&hv.y));
                a0 += e * f0.x;
                a1 += e * f0.y;
                a2 += e * f1.x;
                a3 += e * f1.y;
            }
        }

        // write chunk b+8 into the other buffer; single barrier per chunk
        st[(p ^ 1) * 36 + q * 9 + ql] = make_float2(__int_as_float(nsj), nex);
        __syncwarp();
        p ^= 1;
    }

    // self-loop
    {
        float exs = __expf(lrelu(asv[node] + ad) - m);
        uint2 hv = *reinterpret_cast<const uint2*>(&hbuf[node * HID + ql * 4]);
        float2 f0 = __half22float2(*reinterpret_cast<half2*>(&hv.x));
        float2 f1 = __half22float2(*reinterpret_cast<half2*>(&hv.y));
        a0 += exs * f0.x;
        a1 += exs * f0.y;
        a2 += exs * f1.x;
        a3 += exs * f1.y;
        if (ql == 0) denp += exs;
    }

    // denominator reduce within the 8-lane quarter
#pragma unroll
    for (int o = 4; o; o >>= 1) denp += __shfl_xor_sync(0xffffffffu, denp, o);
    float r = 1.f / (denp + 1e-16f);
    return make_float4(a0 * r, a1 * r, a2 * r, a3 * r);
}

__device__ __forceinline__ void load_deg(int node, int& pre1, int& pre2,
                                         int& pre3, int& deg)
{
    int d0 = g_degK[node];
    int d1 = g_degK[N_NODES + node];
    int d2 = g_degK[2 * N_NODES + node];
    int d3 = g_degK[3 * N_NODES + node];
    pre1 = d0;
    pre2 = d0 + d1;
    pre3 = pre2 + d2;
    deg  = pre3 + d3;
}

// ---------------------------------------------------------------------------
// Fused: layer-1 gather + epilogue + layer-2 transform + attention halves.
// ws2/wd2 (= W2 @ att vectors) computed block-locally (W2 is L2-hot) —
// removes the separate precompute kernel.
// ---------------------------------------------------------------------------
__global__ void __launch_bounds__(256) k_g1t2(
    const float* __restrict__ W2, const float* __restrict__ b1,
    const float* __restrict__ as2, const float* __restrict__ ad2)
{
    __shared__ float2 stage[8][72];      // per warp: 2 buffers * 4 quarters * 9
    __shared__ float  sW2[HID * HID];
    __shared__ float  sxw[8][4 * 33];    // stride 33: conflict-free broadcasts
    __shared__ __align__(16) float s_ws[HID], s_wd[HID];

    for (int i = threadIdx.x; i < HID * HID; i += 256) sW2[i] = W2[i];
    if (threadIdx.x < HID) {
        float ws = 0.f, wd = 0.f;
#pragma unroll
        for (int j = 0; j < HID; j++) {
            float w = W2[threadIdx.x * HID + j];
            ws += w * as2[j];
            wd += w * ad2[j];
        }
        s_ws[threadIdx.x] = ws;
        s_wd[threadIdx.x] = wd;
    }
    __syncthreads();

    int wid  = threadIdx.x >> 5;
    int lane = threadIdx.x & 31;
    int q    = lane >> 3;
    int ql   = lane & 7;
    int node = (blockIdx.x * 8 + wid) * 4 + q;

    int pre1, pre2, pre3, deg;
    load_deg(node, pre1, pre2, pre3, deg);
    int degmax = max(deg, __shfl_xor_sync(0xffffffffu, deg, 8));
    degmax = max(degmax, __shfl_xor_sync(0xffffffffu, degmax, 16));

    float Amax0 = dec2(g_amax_enc[0]);
    float4 v = gather_quarter(node, ql, q, stage[wid], degmax, deg,
                              pre1, pre2, pre3, g_as, g_ad, g_h16, Amax0);
    float4 bb = *reinterpret_cast<const float4*>(&b1[ql * 4]);
    float v0 = fmaxf(v.x + bb.x, 0.f);
    float v1 = fmaxf(v.y + bb.y, 0.f);
    float v2 = fmaxf(v.z + bb.z, 0.f);
    float v3 = fmaxf(v.w + bb.w, 0.f);

    // layer-2 attention halves on x2 (pre-matmul, via W2@att vectors)
    float4 ws = *reinterpret_cast<const float4*>(&s_ws[ql * 4]);
    float4 wd = *reinterpret_cast<const float4*>(&s_wd[ql * 4]);
    float s = v0 * ws.x + v1 * ws.y + v2 * ws.z + v3 * ws.w;
    float d = v0 * wd.x + v1 * wd.y + v2 * wd.z + v3 * wd.w;
#pragma unroll
    for (int o = 4; o; o >>= 1) {
        s += __shfl_xor_sync(0xffffffffu, s, o);
        d += __shfl_xor_sync(0xffffffffu, d, o);
    }
    if (ql == 0) { g_as2[node] = s; g_ad2[node] = d; }

    // layer-2 transform: h2 = x2 @ W2 within the quarter
    float* xq = &sxw[wid][q * 33];
    xq[ql * 4]     = v0;
    xq[ql * 4 + 1] = v1;
    xq[ql * 4 + 2] = v2;
    xq[ql * 4 + 3] = v3;
    __syncwarp();
    float h0 = 0.f, h1 = 0.f, h2 = 0.f, h3 = 0.f;
#pragma unroll
    for (int i = 0; i < HID; i++) {
        float xi = xq[i];
        float4 w = *reinterpret_cast<const float4*>(&sW2[i * HID + ql * 4]);
        h0 += xi * w.x;
        h1 += xi * w.y;
        h2 += xi * w.z;
        h3 += xi * w.w;
    }
    uint2 hv;
    *reinterpret_cast<half2*>(&hv.x) = __floats2half2_rn(h0, h1);
    *reinterpret_cast<half2*>(&hv.y) = __floats2half2_rn(h2, h3);
    *reinterpret_cast<uint2*>(&g_h16b[node * HID + ql * 4]) = hv;

    // amax slot 1
    __shared__ float wmax[8];
    float mw = fmaxf(s, __shfl_xor_sync(0xffffffffu, s, 8));
    mw = fmaxf(mw, __shfl_xor_sync(0xffffffffu, mw, 16));
    if (lane == 0) wmax[wid] = mw;
    __syncthreads();
    if (threadIdx.x == 0) {
        float mb = wmax[0];
#pragma unroll
        for (int i = 1; i < 8; i++) mb = fmaxf(mb, wmax[i]);
        atomicMax(&g_amax_enc[1], enc2(mb));
    }
}

// ---------------------------------------------------------------------------
// Layer-2 gather + epilogue + linear head.
// ---------------------------------------------------------------------------
__global__ void __launch_bounds__(256) k_gather2(
    const float* __restrict__ b2, const float* __restrict__ Wl,
    const float* __restrict__ bl, float* __restrict__ out)
{
    __shared__ float2 stage[8][72];
    int wid  = threadIdx.x >> 5;
    int lane = threadIdx.x & 31;
    int q    = lane >> 3;
    int ql   = lane & 7;
    int node = (blockIdx.x * 8 + wid) * 4 + q;

    int pre1, pre2, pre3, deg;
    load_deg(node, pre1, pre2, pre3, deg);
    int degmax = max(deg, __shfl_xor_sync(0xffffffffu, deg, 8));
    degmax = max(degmax, __shfl_xor_sync(0xffffffffu, degmax, 16));

    float Amax1 = dec2(g_amax_enc[1]);
    float4 v = gather_quarter(node, ql, q, stage[wid], degmax, deg,
                              pre1, pre2, pre3, g_as2, g_ad2, g_h16b, Amax1);
    float4 bb = *reinterpret_cast<const float4*>(&b2[ql * 4]);
    float v0 = fmaxf(v.x + bb.x, 0.f);
    float v1 = fmaxf(v.y + bb.y, 0.f);
    float v2 = fmaxf(v.z + bb.z, 0.f);
    float v3 = fmaxf(v.w + bb.w, 0.f);

    float4 wl = *reinterpret_cast<const float4*>(&Wl[ql * 4]);
    float p = v0 * wl.x + v1 * wl.y + v2 * wl.z + v3 * wl.w;
#pragma unroll
    for (int o = 4; o; o >>= 1) p += __shfl_xor_sync(0xffffffffu, p, o);
    if (ql == 0) out[node] = p + bl[0];
}

// ---------------------------------------------------------------------------
extern "C" void kernel_launch(void* const* d_in, const int* in_sizes, int n_in,
                              void* d_out, int out_size)
{
    const float* x   = (const float*)d_in[0];
    const int*  eidx = (const int*)d_in[1];     // [2, E]
    const float* W1  = (const float*)d_in[2];
    const float* as1 = (const float*)d_in[3];
    const float* ad1 = (const float*)d_in[4];
    const float* b1  = (const float*)d_in[5];
    const float* W2  = (const float*)d_in[6];
    const float* as2 = (const float*)d_in[7];
    const float* ad2 = (const float*)d_in[8];
    const float* b2  = (const float*)d_in[9];
    const float* Wl  = (const float*)d_in[10];
    const float* bl  = (const float*)d_in[11];
    float*       out = (float*)d_out;

    const int4* src4 = (const int4*)eidx;
    const int4* dst4 = (const int4*)(eidx + N_EDGES);

    void* degKPtr = nullptr;
    cudaGetSymbolAddress(&degKPtr, g_degK);
    cudaMemsetAsync(degKPtr, 0, 4 * N_NODES * sizeof(int));
    void* amaxPtr = nullptr;
    cudaGetSymbolAddress(&amaxPtr, g_amax_enc);
    cudaMemsetAsync(amaxPtr, 0, 2 * sizeof(unsigned));   // 0 == enc2(-inf)

    k_p1<<<NODE_BLOCKS + EDGE4_BLOCKS, 256>>>(x, W1, as1, ad1, src4, dst4);
    k_g1t2<<<GATHER_BLOCKS, 256>>>(W2, b1, as2, ad2);
    k_gather2<<<GATHER_BLOCKS, 256>>>(b2, Wl, bl, out);
}

// round 15
// speedup vs baseline: 1.1088x; 1.1088x over previous
#include <cuda_runtime.h>
#include <cuda_fp16.h>

#define N_NODES 100000
#define N_EDGES 3200000
#define HID     32
#define NEG     0.2f
#define ENC_SHIFT 0x007FFFFFu                     // enc(-inf); enc2(-inf) == 0
#define CAP     160                               // CSR slots per node (4 segments)
#define CAP4    40                                // slots per replica segment
#define NODE_BLOCKS  ((N_NODES + 7) / 8)          // 12500 (transform part of k_p1)
#define EDGE4        (N_EDGES / 4)                // 800000
#define EDGE4_BLOCKS ((EDGE4 + 255) / 256)        // 3125
#define GATHER_BLOCKS (N_NODES / 32)              // 3125 (quarter-warp: 32 nodes/block)

// ---- static device scratch ----
__device__ __align__(16) __half g_h16 [N_NODES * HID];  // layer-1 features (fp16)
__device__ __align__(16) __half g_h16b[N_NODES * HID];  // layer-2 features (fp16)
__device__ float    g_as [N_NODES], g_ad [N_NODES];     // layer-1 attention halves
__device__ float    g_as2[N_NODES], g_ad2[N_NODES];     // layer-2 attention halves
__device__ int      g_degK[4 * N_NODES];                // 4-replica degree counters
__device__ int      g_csr[N_NODES * CAP];               // implicit-offset CSR (64MB)
__device__ unsigned g_amax_enc[2];                      // memset-0 == enc2(-inf)

// shifted order-preserving float<->uint encoding: 0 decodes to -inf
__device__ __forceinline__ unsigned enc2(float f) {
    unsigned u = __float_as_uint(f);
    unsigned e = (u & 0x80000000u) ? ~u : (u | 0x80000000u);
    return e - ENC_SHIFT;
}
__device__ __forceinline__ float dec2(unsigned v) {
    unsigned u = v + ENC_SHIFT;
    return (u & 0x80000000u) ? __uint_as_float(u ^ 0x80000000u)
                             : __uint_as_float(~u);
}
__device__ __forceinline__ float lrelu(float x) { return x >= 0.f ? x : NEG * x; }

// ---------------------------------------------------------------------------
// Phase 1 (fused): blocks [0, NODE_BLOCKS) = layer-1 transform (node-first
// ordering measured fastest); blocks beyond = single-pass implicit-offset CSR
// build: edge 4i+k -> rank = atomicAdd(degK[k][d]); csr[d*CAP+k*CAP4+rank]=s.
// ---------------------------------------------------------------------------
__global__ void __launch_bounds__(256) k_p1(
    const float* __restrict__ x, const float* __restrict__ W1,
    const float* __restrict__ aw_s, const float* __restrict__ aw_d,
    const int4* __restrict__ src4, const int4* __restrict__ dst4)
{
    if (blockIdx.x >= NODE_BLOCKS) {
        int i = (blockIdx.x - NODE_BLOCKS) * 256 + threadIdx.x;
        if (i < EDGE4) {
            int4 d = dst4[i];
            int4 s = src4[i];
            int r0 = atomicAdd(&g_degK[              d.x], 1);
            int r1 = atomicAdd(&g_degK[    N_NODES + d.y], 1);
            int r2 = atomicAdd(&g_degK[2 * N_NODES + d.z], 1);
            int r3 = atomicAdd(&g_degK[3 * N_NODES + d.w], 1);
            g_csr[d.x * CAP            + r0] = s.x;
            g_csr[d.y * CAP +     CAP4 + r1] = s.y;
            g_csr[d.z * CAP + 2 * CAP4 + r2] = s.z;
            g_csr[d.w * CAP + 3 * CAP4 + r3] = s.w;
        }
        return;
    }

    int wid  = threadIdx.x >> 5;
    int lane = threadIdx.x & 31;
    int node = blockIdx.x * 8 + wid;

    float s = -3.4e38f;
    if (node < N_NODES) {
        float xv = (lane < 3) ? x[node * 3 + lane] : 0.f;
        float x0 = __shfl_sync(0xffffffffu, xv, 0);
        float x1 = __shfl_sync(0xffffffffu, xv, 1);
        float x2 = __shfl_sync(0xffffffffu, xv, 2);

        float h = x0 * W1[lane] + x1 * W1[HID + lane] + x2 * W1[2 * HID + lane];
        g_h16[node * HID + lane] = __float2half(h);

        s = h * aw_s[lane];
        float d = h * aw_d[lane];
#pragma unroll
        for (int o = 16; o; o >>= 1) {
            s += __shfl_xor_sync(0xffffffffu, s, o);
            d += __shfl_xor_sync(0xffffffffu, d, o);
        }
        if (lane == 0) { g_as[node] = s; g_ad[node] = d; }
    }
    __shared__ float warp_s[8];
    if (lane == 0) warp_s[wid] = s;
    __syncthreads();
    if (threadIdx.x == 0) {
        float m = warp_s[0];
#pragma unroll
        for (int i = 1; i < 8; i++) m = fmaxf(m, warp_s[i]);
        atomicMax(&g_amax_enc[0], enc2(m));
    }
}

// ---------------------------------------------------------------------------
// Quarter-warp gather (single-buffer stage — measured best): 8 lanes own one
// node (consecutive nodes per warp for locality); lane ql handles features
// [4ql, 4ql+4) as half4 (uint2). Padded entries carry ex = 0; the quarter-
// uniform e>0 guard keeps padding off the memory path.
// ---------------------------------------------------------------------------
__device__ __forceinline__ float4 gather_quarter(
    int node, int ql, int q, float2* __restrict__ st,
    int degmax, int deg, int pre1, int pre2, int pre3,
    const float* __restrict__ asv, const float* __restrict__ adv,
    const __half* __restrict__ hbuf, float Amax)
{
    const float ad = adv[node];
    const float m  = lrelu(Amax + ad);
    const int base = node * CAP;

    float a0 = 0.f, a1 = 0.f, a2 = 0.f, a3 = 0.f, denp = 0.f;

    // prologue: chunk-0 edge for this lane
    int sj = 0; float ex = 0.f;
    if (ql < deg) {
        int idx = ql, slot;
        if      (idx < pre1) slot = idx;
        else if (idx < pre2) slot =     CAP4 + idx - pre1;
        else if (idx < pre3) slot = 2 * CAP4 + idx - pre2;
        else                 slot = 3 * CAP4 + idx - pre3;
        sj = g_csr[base + slot];
        ex = __expf(lrelu(asv[sj] + ad) - m);
    }

    for (int b = 0; b < degmax; b += 8) {
        denp += ex;
        st[q * 9 + ql] = make_float2(__int_as_float(sj), ex);
        __syncwarp();

        // prefetch next chunk (overlaps with consume below)
        int nidx = b + 8 + ql;
        int nsj = 0; float nex = 0.f;
        if (nidx < deg) {
            int slot;
            if      (nidx < pre1) slot = nidx;
            else if (nidx < pre2) slot =     CAP4 + nidx - pre1;
            else if (nidx < pre3) slot = 2 * CAP4 + nidx - pre2;
            else                  slot = 3 * CAP4 + nidx - pre3;
            nsj = g_csr[base + slot];
            nex = __expf(lrelu(asv[nsj] + ad) - m);
        }

        // consume chunk; e is quarter-uniform so the guard predicates away
        // the LDG + FMAs for padded edges without divergence cost
#pragma unroll
        for (int j = 0; j < 8; j++) {
            float2 p = st[q * 9 + j];
            float e  = p.y;
            if (e > 0.f) {
                int   sE = __float_as_int(p.x);
                uint2 hv = *reinterpret_cast<const uint2*>(&hbuf[sE * HID + ql * 4]);
                float2 f0 = __half22float2(*reinterpret_cast<half2*>(&hv.x));
                float2 f1 = __half22float2(*reinterpret_cast<half2*>(&hv.y));
                a0 += e * f0.x;
                a1 += e * f0.y;
                a2 += e * f1.x;
                a3 += e * f1.y;
            }
        }
        __syncwarp();
        sj = nsj; ex = nex;
    }

    // self-loop
    {
        float exs = __expf(lrelu(asv[node] + ad) - m);
        uint2 hv = *reinterpret_cast<const uint2*>(&hbuf[node * HID + ql * 4]);
        float2 f0 = __half22float2(*reinterpret_cast<half2*>(&hv.x));
        float2 f1 = __half22float2(*reinterpret_cast<half2*>(&hv.y));
        a0 += exs * f0.x;
        a1 += exs * f0.y;
        a2 += exs * f1.x;
        a3 += exs * f1.y;
        if (ql == 0) denp += exs;
    }

    // denominator reduce within the 8-lane quarter
#pragma unroll
    for (int o = 4; o; o >>= 1) denp += __shfl_xor_sync(0xffffffffu, denp, o);
    float r = 1.f / (denp + 1e-16f);
    return make_float4(a0 * r, a1 * r, a2 * r, a3 * r);
}

__device__ __forceinline__ void load_deg(int node, int& pre1, int& pre2,
                                         int& pre3, int& deg)
{
    int d0 = g_degK[node];
    int d1 = g_degK[N_NODES + node];
    int d2 = g_degK[2 * N_NODES + node];
    int d3 = g_degK[3 * N_NODES + node];
    pre1 = d0;
    pre2 = d0 + d1;
    pre3 = pre2 + d2;
    deg  = pre3 + d3;
}

// ---------------------------------------------------------------------------
// Fused: layer-1 gather + epilogue + layer-2 transform + attention halves.
// ws2/wd2 (= W2 @ att vectors) computed block-locally (W2 is L2-hot) —
// replaces the separate precompute kernel.
// ---------------------------------------------------------------------------
__global__ void __launch_bounds__(256) k_g1t2(
    const float* __restrict__ W2, const float* __restrict__ b1,
    const float* __restrict__ as2, const float* __restrict__ ad2)
{
    __shared__ float2 stage[8][36];      // 4 quarters * stride 9
    __shared__ float  sW2[HID * HID];
    __shared__ float  sxw[8][4 * 33];    // stride 33: conflict-free broadcasts
    __shared__ __align__(16) float s_ws[HID], s_wd[HID];

    for (int i = threadIdx.x; i < HID * HID; i += 256) sW2[i] = W2[i];
    if (threadIdx.x < HID) {
        float ws = 0.f, wd = 0.f;
#pragma unroll
        for (int j = 0; j < HID; j++) {
            float w = W2[threadIdx.x * HID + j];
            ws += w * as2[j];
            wd += w * ad2[j];
        }
        s_ws[threadIdx.x] = ws;
        s_wd[threadIdx.x] = wd;
    }
    __syncthreads();

    int wid  = threadIdx.x >> 5;
    int lane = threadIdx.x & 31;
    int q    = lane >> 3;
    int ql   = lane & 7;
    int node = (blockIdx.x * 8 + wid) * 4 + q;

    int pre1, pre2, pre3, deg;
    load_deg(node, pre1, pre2, pre3, deg);
    int degmax = max(deg, __shfl_xor_sync(0xffffffffu, deg, 8));
    degmax = max(degmax, __shfl_xor_sync(0xffffffffu, degmax, 16));

    float Amax0 = dec2(g_amax_enc[0]);
    float4 v = gather_quarter(node, ql, q, stage[wid], degmax, deg,
                              pre1, pre2, pre3, g_as, g_ad, g_h16, Amax0);
    float4 bb = *reinterpret_cast<const float4*>(&b1[ql * 4]);
    float v0 = fmaxf(v.x + bb.x, 0.f);
    float v1 = fmaxf(v.y + bb.y, 0.f);
    float v2 = fmaxf(v.z + bb.z, 0.f);
    float v3 = fmaxf(v.w + bb.w, 0.f);

    // layer-2 attention halves on x2 (pre-matmul, via W2@att vectors)
    float4 ws = *reinterpret_cast<const float4*>(&s_ws[ql * 4]);
    float4 wd = *reinterpret_cast<const float4*>(&s_wd[ql * 4]);
    float s = v0 * ws.x + v1 * ws.y + v2 * ws.z + v3 * ws.w;
    float d = v0 * wd.x + v1 * wd.y + v2 * wd.z + v3 * wd.w;
#pragma unroll
    for (int o = 4; o; o >>= 1) {
        s += __shfl_xor_sync(0xffffffffu, s, o);
        d += __shfl_xor_sync(0xffffffffu, d, o);
    }
    if (ql == 0) { g_as2[node] = s; g_ad2[node] = d; }

    // layer-2 transform: h2 = x2 @ W2 within the quarter
    float* xq = &sxw[wid][q * 33];
    xq[ql * 4]     = v0;
    xq[ql * 4 + 1] = v1;
    xq[ql * 4 + 2] = v2;
    xq[ql * 4 + 3] = v3;
    __syncwarp();
    float h0 = 0.f, h1 = 0.f, h2 = 0.f, h3 = 0.f;
#pragma unroll
    for (int i = 0; i < HID; i++) {
        float xi = xq[i];
        float4 w = *reinterpret_cast<const float4*>(&sW2[i * HID + ql * 4]);
        h0 += xi * w.x;
        h1 += xi * w.y;
        h2 += xi * w.z;
        h3 += xi * w.w;
    }
    uint2 hv;
    *reinterpret_cast<half2*>(&hv.x) = __floats2half2_rn(h0, h1);
    *reinterpret_cast<half2*>(&hv.y) = __floats2half2_rn(h2, h3);
    *reinterpret_cast<uint2*>(&g_h16b[node * HID + ql * 4]) = hv;

    // amax slot 1
    __shared__ float wmax[8];
    float mw = fmaxf(s, __shfl_xor_sync(0xffffffffu, s, 8));
    mw = fmaxf(mw, __shfl_xor_sync(0xffffffffu, mw, 16));
    if (lane == 0) wmax[wid] = mw;
    __syncthreads();
    if (threadIdx.x == 0) {
        float mb = wmax[0];
#pragma unroll
        for (int i = 1; i < 8; i++) mb = fmaxf(mb, wmax[i]);
        atomicMax(&g_amax_enc[1], enc2(mb));
    }
}

// ---------------------------------------------------------------------------
// Layer-2 gather + epilogue + linear head.
// ---------------------------------------------------------------------------
__global__ void __launch_bounds__(256) k_gather2(
    const float* __restrict__ b2, const float* __restrict__ Wl,
    const float* __restrict__ bl, float* __restrict__ out)
{
    __shared__ float2 stage[8][36];
    int wid  = threadIdx.x >> 5;
    int lane = threadIdx.x & 31;
    int q    = lane >> 3;
    int ql   = lane & 7;
    int node = (blockIdx.x * 8 + wid) * 4 + q;

    int pre1, pre2, pre3, deg;
    load_deg(node, pre1, pre2, pre3, deg);
    int degmax = max(deg, __shfl_xor_sync(0xffffffffu, deg, 8));
    degmax = max(degmax, __shfl_xor_sync(0xffffffffu, degmax, 16));

    float Amax1 = dec2(g_amax_enc[1]);
    float4 v = gather_quarter(node, ql, q, stage[wid], degmax, deg,
                              pre1, pre2, pre3, g_as2, g_ad2, g_h16b, Amax1);
    float4 bb = *reinterpret_cast<const float4*>(&b2[ql * 4]);
    float v0 = fmaxf(v.x + bb.x, 0.f);
    float v1 = fmaxf(v.y + bb.y, 0.f);
    float v2 = fmaxf(v.z + bb.z, 0.f);
    float v3 = fmaxf(v.w + bb.w, 0.f);

    float4 wl = *reinterpret_cast<const float4*>(&Wl[ql * 4]);
    float p = v0 * wl.x + v1 * wl.y + v2 * wl.z + v3 * wl.w;
#pragma unroll
    for (int o = 4; o; o >>= 1) p += __shfl_xor_sync(0xffffffffu, p, o);
    if (ql == 0) out[node] = p + bl[0];
}

// ---------------------------------------------------------------------------
extern "C" void kernel_launch(void* const* d_in, const int* in_sizes, int n_in,
                              void* d_out, int out_size)
{
    const float* x   = (const float*)d_in[0];
    const int*  eidx = (const int*)d_in[1];     // [2, E]
    const float* W1  = (const float*)d_in[2];
    const float* as1 = (const float*)d_in[3];
    const float* ad1 = (const float*)d_in[4];
    const float* b1  = (const float*)d_in[5];
    const float* W2  = (const float*)d_in[6];
    const float* as2 = (const float*)d_in[7];
    const float* ad2 = (const float*)d_in[8];
    const float* b2  = (const float*)d_in[9];
    const float* Wl  = (const float*)d_in[10];
    const float* bl  = (const float*)d_in[11];
    float*       out = (float*)d_out;

    const int4* src4 = (const int4*)eidx;
    const int4* dst4 = (const int4*)(eidx + N_EDGES);

    void* degKPtr = nullptr;
    cudaGetSymbolAddress(&degKPtr, g_degK);
    cudaMemsetAsync(degKPtr, 0, 4 * N_NODES * sizeof(int));
    void* amaxPtr = nullptr;
    cudaGetSymbolAddress(&amaxPtr, g_amax_enc);
    cudaMemsetAsync(amaxPtr, 0, 2 * sizeof(unsigned));   // 0 == enc2(-inf)

    k_p1<<<NODE_BLOCKS + EDGE4_BLOCKS, 256>>>(x, W1, as1, ad1, src4, dst4);
    k_g1t2<<<GATHER_BLOCKS, 256>>>(W2, b1, as2, ad2);
    k_gather2<<<GATHER_BLOCKS, 256>>>(b2, Wl, bl, out);
}

// round 16
// speedup vs baseline: 1.1938x; 1.0766x over previous
#include <cuda_runtime.h>
#include <cuda_fp16.h>

#define N_NODES 100000
#define N_EDGES 3200000
#define HID     32
#define NEG     0.2f
#define ENC_NEGINF 0x007FFFFFu
#define CAP     160                               // CSR slots per node (4 segments)
#define CAP4    40                                // slots per replica segment
#define NODE_BLOCKS  ((N_NODES + 7) / 8)          // 12500 (transform part of k_p1)
#define EDGE4        (N_EDGES / 4)                // 800000
#define EDGE4_BLOCKS ((EDGE4 + 255) / 256)        // 3125
#define GATHER_BLOCKS (N_NODES / 32)              // 3125 (quarter-warp: 32 nodes/block)

// ---- static device scratch ----
__device__ __align__(16) __half g_h16 [N_NODES * HID];  // layer-1 features (fp16)
__device__ __align__(16) __half g_h16b[N_NODES * HID];  // layer-2 features (fp16)
__device__ float    g_as [N_NODES], g_ad [N_NODES];     // layer-1 attention halves
__device__ float    g_as2[N_NODES], g_ad2[N_NODES];     // layer-2 attention halves
__device__ int      g_degK[4 * N_NODES];                // 4-replica degree counters
__device__ int      g_csr[N_NODES * CAP];               // implicit-offset CSR (64MB)
__device__ unsigned g_amax_enc[2];
__device__ __align__(16) float g_ws2[HID], g_wd2[HID];  // W2 @ att_{src,dst}2

__device__ __forceinline__ unsigned encf(float f) {
    unsigned u = __float_as_uint(f);
    return (u & 0x80000000u) ? ~u : (u | 0x80000000u);
}
__device__ __forceinline__ float decf(unsigned u) {
    return (u & 0x80000000u) ? __uint_as_float(u ^ 0x80000000u)
                             : __uint_as_float(~u);
}
__device__ __forceinline__ float lrelu(float x) { return x >= 0.f ? x : NEG * x; }

// ---------------------------------------------------------------------------
// Precompute ONCE: amax init + ws2/wd2 = W2 @ att vectors (one warp).
// Doing this per-block in k_g1t2 costs ~100MB of L2 traffic (measured +12us);
// the dedicated tiny kernel is the cheaper form.
// ---------------------------------------------------------------------------
__global__ void k_precomp(const float* __restrict__ W2,
                          const float* __restrict__ as2,
                          const float* __restrict__ ad2) {
    int i = threadIdx.x;
    if (i == 0) {
        g_amax_enc[0] = ENC_NEGINF;
        g_amax_enc[1] = ENC_NEGINF;
    }
    float ws = 0.f, wd = 0.f;
#pragma unroll
    for (int j = 0; j < HID; j++) {
        float w = W2[i * HID + j];
        ws += w * as2[j];
        wd += w * ad2[j];
    }
    g_ws2[i] = ws;
    g_wd2[i] = wd;
}

// ---------------------------------------------------------------------------
// Phase 1 (fused): blocks [0, NODE_BLOCKS) = layer-1 transform (node-first
// ordering measured fastest); blocks beyond = single-pass implicit-offset CSR
// build: edge 4i+k -> rank = atomicAdd(degK[k][d]); csr[d*CAP+k*CAP4+rank]=s.
// ---------------------------------------------------------------------------
__global__ void __launch_bounds__(256) k_p1(
    const float* __restrict__ x, const float* __restrict__ W1,
    const float* __restrict__ aw_s, const float* __restrict__ aw_d,
    const int4* __restrict__ src4, const int4* __restrict__ dst4)
{
    if (blockIdx.x >= NODE_BLOCKS) {
        int i = (blockIdx.x - NODE_BLOCKS) * 256 + threadIdx.x;
        if (i < EDGE4) {
            int4 d = dst4[i];
            int4 s = src4[i];
            int r0 = atomicAdd(&g_degK[              d.x], 1);
            int r1 = atomicAdd(&g_degK[    N_NODES + d.y], 1);
            int r2 = atomicAdd(&g_degK[2 * N_NODES + d.z], 1);
            int r3 = atomicAdd(&g_degK[3 * N_NODES + d.w], 1);
            g_csr[d.x * CAP            + r0] = s.x;
            g_csr[d.y * CAP +     CAP4 + r1] = s.y;
            g_csr[d.z * CAP + 2 * CAP4 + r2] = s.z;
            g_csr[d.w * CAP + 3 * CAP4 + r3] = s.w;
        }
        return;
    }

    int wid  = threadIdx.x >> 5;
    int lane = threadIdx.x & 31;
    int node = blockIdx.x * 8 + wid;

    float s = -3.4e38f;
    if (node < N_NODES) {
        float xv = (lane < 3) ? x[node * 3 + lane] : 0.f;
        float x0 = __shfl_sync(0xffffffffu, xv, 0);
        float x1 = __shfl_sync(0xffffffffu, xv, 1);
        float x2 = __shfl_sync(0xffffffffu, xv, 2);

        float h = x0 * W1[lane] + x1 * W1[HID + lane] + x2 * W1[2 * HID + lane];
        g_h16[node * HID + lane] = __float2half(h);

        s = h * aw_s[lane];
        float d = h * aw_d[lane];
#pragma unroll
        for (int o = 16; o; o >>= 1) {
            s += __shfl_xor_sync(0xffffffffu, s, o);
            d += __shfl_xor_sync(0xffffffffu, d, o);
        }
        if (lane == 0) { g_as[node] = s; g_ad[node] = d; }
    }
    __shared__ float warp_s[8];
    if (lane == 0) warp_s[wid] = s;
    __syncthreads();
    if (threadIdx.x == 0) {
        float m = warp_s[0];
#pragma unroll
        for (int i = 1; i < 8; i++) m = fmaxf(m, warp_s[i]);
        atomicMax(&g_amax_enc[0], encf(m));
    }
}

// ---------------------------------------------------------------------------
// Quarter-warp gather (single-buffer stage — measured best): 8 lanes own one
// node (consecutive nodes per warp for locality); lane ql handles features
// [4ql, 4ql+4) as half4 (uint2). Padded entries carry ex = 0; the quarter-
// uniform e>0 guard keeps padding off the memory path.
// ---------------------------------------------------------------------------
__device__ __forceinline__ float4 gather_quarter(
    int node, int ql, int q, float2* __restrict__ st,
    int degmax, int deg, int pre1, int pre2, int pre3,
    const float* __restrict__ asv, const float* __restrict__ adv,
    const __half* __restrict__ hbuf, float Amax)
{
    const float ad = adv[node];
    const float m  = lrelu(Amax + ad);
    const int base = node * CAP;

    float a0 = 0.f, a1 = 0.f, a2 = 0.f, a3 = 0.f, denp = 0.f;

    // prologue: chunk-0 edge for this lane
    int sj = 0; float ex = 0.f;
    if (ql < deg) {
        int idx = ql, slot;
        if      (idx < pre1) slot = idx;
        else if (idx < pre2) slot =     CAP4 + idx - pre1;
        else if (idx < pre3) slot = 2 * CAP4 + idx - pre2;
        else                 slot = 3 * CAP4 + idx - pre3;
        sj = g_csr[base + slot];
        ex = __expf(lrelu(asv[sj] + ad) - m);
    }

    for (int b = 0; b < degmax; b += 8) {
        denp += ex;
        st[q * 9 + ql] = make_float2(__int_as_float(sj), ex);
        __syncwarp();

        // prefetch next chunk (overlaps with consume below)
        int nidx = b + 8 + ql;
        int nsj = 0; float nex = 0.f;
        if (nidx < deg) {
            int slot;
            if      (nidx < pre1) slot = nidx;
            else if (nidx < pre2) slot =     CAP4 + nidx - pre1;
            else if (nidx < pre3) slot = 2 * CAP4 + nidx - pre2;
            else                  slot = 3 * CAP4 + nidx - pre3;
            nsj = g_csr[base + slot];
            nex = __expf(lrelu(asv[nsj] + ad) - m);
        }

        // consume chunk; e is quarter-uniform so the guard predicates away
        // the LDG + FMAs for padded edges without divergence cost
#pragma unroll
        for (int j = 0; j < 8; j++) {
            float2 p = st[q * 9 + j];
            float e  = p.y;
            if (e > 0.f) {
                int   sE = __float_as_int(p.x);
                uint2 hv = *reinterpret_cast<const uint2*>(&hbuf[sE * HID + ql * 4]);
                float2 f0 = __half22float2(*reinterpret_cast<half2*>(&hv.x));
                float2 f1 = __half22float2(*reinterpret_cast<half2*>(&hv.y));
                a0 += e * f0.x;
                a1 += e * f0.y;
                a2 += e * f1.x;
                a3 += e * f1.y;
            }
        }
        __syncwarp();
        sj = nsj; ex = nex;
    }

    // self-loop
    {
        float exs = __expf(lrelu(asv[node] + ad) - m);
        uint2 hv = *reinterpret_cast<const uint2*>(&hbuf[node * HID + ql * 4]);
        float2 f0 = __half22float2(*reinterpret_cast<half2*>(&hv.x));
        float2 f1 = __half22float2(*reinterpret_cast<half2*>(&hv.y));
        a0 += exs * f0.x;
        a1 += exs * f0.y;
        a2 += exs * f1.x;
        a3 += exs * f1.y;
        if (ql == 0) denp += exs;
    }

    // denominator reduce within the 8-lane quarter
#pragma unroll
    for (int o = 4; o; o >>= 1) denp += __shfl_xor_sync(0xffffffffu, denp, o);
    float r = 1.f / (denp + 1e-16f);
    return make_float4(a0 * r, a1 * r, a2 * r, a3 * r);
}

__device__ __forceinline__ void load_deg(int node, int& pre1, int& pre2,
                                         int& pre3, int& deg)
{
    int d0 = g_degK[node];
    int d1 = g_degK[N_NODES + node];
    int d2 = g_degK[2 * N_NODES + node];
    int d3 = g_degK[3 * N_NODES + node];
    pre1 = d0;
    pre2 = d0 + d1;
    pre3 = pre2 + d2;
    deg  = pre3 + d3;
}

// ---------------------------------------------------------------------------
// Fused: layer-1 gather + epilogue + layer-2 transform + attention halves.
// ---------------------------------------------------------------------------
__global__ void __launch_bounds__(256) k_g1t2(
    const float* __restrict__ W2, const float* __restrict__ b1)
{
    __shared__ float2 stage[8][36];      // 4 quarters * stride 9
    __shared__ float  sW2[HID * HID];
    __shared__ float  sxw[8][4 * 33];    // stride 33: conflict-free broadcasts

    for (int i = threadIdx.x; i < HID * HID; i += 256) sW2[i] = W2[i];
    __syncthreads();

    int wid  = threadIdx.x >> 5;
    int lane = threadIdx.x & 31;
    int q    = lane >> 3;
    int ql   = lane & 7;
    int node = (blockIdx.x * 8 + wid) * 4 + q;

    int pre1, pre2, pre3, deg;
    load_deg(node, pre1, pre2, pre3, deg);
    int degmax = max(deg, __shfl_xor_sync(0xffffffffu, deg, 8));
    degmax = max(degmax, __shfl_xor_sync(0xffffffffu, degmax, 16));

    float Amax0 = decf(g_amax_enc[0]);
    float4 v = gather_quarter(node, ql, q, stage[wid], degmax, deg,
                              pre1, pre2, pre3, g_as, g_ad, g_h16, Amax0);
    float4 bb = *reinterpret_cast<const float4*>(&b1[ql * 4]);
    float v0 = fmaxf(v.x + bb.x, 0.f);
    float v1 = fmaxf(v.y + bb.y, 0.f);
    float v2 = fmaxf(v.z + bb.z, 0.f);
    float v3 = fmaxf(v.w + bb.w, 0.f);

    // layer-2 attention halves on x2 (pre-matmul, via W2@att vectors)
    float4 ws = *reinterpret_cast<const float4*>(&g_ws2[ql * 4]);
    float4 wd = *reinterpret_cast<const float4*>(&g_wd2[ql * 4]);
    float s = v0 * ws.x + v1 * ws.y + v2 * ws.z + v3 * ws.w;
    float d = v0 * wd.x + v1 * wd.y + v2 * wd.z + v3 * wd.w;
#pragma unroll
    for (int o = 4; o; o >>= 1) {
        s += __shfl_xor_sync(0xffffffffu, s, o);
        d += __shfl_xor_sync(0xffffffffu, d, o);
    }
    if (ql == 0) { g_as2[node] = s; g_ad2[node] = d; }

    // layer-2 transform: h2 = x2 @ W2 within the quarter
    float* xq = &sxw[wid][q * 33];
    xq[ql * 4]     = v0;
    xq[ql * 4 + 1] = v1;
    xq[ql * 4 + 2] = v2;
    xq[ql * 4 + 3] = v3;
    __syncwarp();
    float h0 = 0.f, h1 = 0.f, h2 = 0.f, h3 = 0.f;
#pragma unroll
    for (int i = 0; i < HID; i++) {
        float xi = xq[i];
        float4 w = *reinterpret_cast<const float4*>(&sW2[i * HID + ql * 4]);
        h0 += xi * w.x;
        h1 += xi * w.y;
        h2 += xi * w.z;
        h3 += xi * w.w;
    }
    uint2 hv;
    *reinterpret_cast<half2*>(&hv.x) = __floats2half2_rn(h0, h1);
    *reinterpret_cast<half2*>(&hv.y) = __floats2half2_rn(h2, h3);
    *reinterpret_cast<uint2*>(&g_h16b[node * HID + ql * 4]) = hv;

    // amax slot 1
    __shared__ float wmax[8];
    float mw = fmaxf(s, __shfl_xor_sync(0xffffffffu, s, 8));
    mw = fmaxf(mw, __shfl_xor_sync(0xffffffffu, mw, 16));
    if (lane == 0) wmax[wid] = mw;
    __syncthreads();
    if (threadIdx.x == 0) {
        float mb = wmax[0];
#pragma unroll
        for (int i = 1; i < 8; i++) mb = fmaxf(mb, wmax[i]);
        atomicMax(&g_amax_enc[1], encf(mb));
    }
}

// ---------------------------------------------------------------------------
// Layer-2 gather + epilogue + linear head.
// ---------------------------------------------------------------------------
__global__ void __launch_bounds__(256) k_gather2(
    const float* __restrict__ b2, const float* __restrict__ Wl,
    const float* __restrict__ bl, float* __restrict__ out)
{
    __shared__ float2 stage[8][36];
    int wid  = threadIdx.x >> 5;
    int lane = threadIdx.x & 31;
    int q    = lane >> 3;
    int ql   = lane & 7;
    int node = (blockIdx.x * 8 + wid) * 4 + q;

    int pre1, pre2, pre3, deg;
    load_deg(node, pre1, pre2, pre3, deg);
    int degmax = max(deg, __shfl_xor_sync(0xffffffffu, deg, 8));
    degmax = max(degmax, __shfl_xor_sync(0xffffffffu, degmax, 16));

    float Amax1 = decf(g_amax_enc[1]);
    float4 v = gather_quarter(node, ql, q, stage[wid], degmax, deg,
                              pre1, pre2, pre3, g_as2, g_ad2, g_h16b, Amax1);
    float4 bb = *reinterpret_cast<const float4*>(&b2[ql * 4]);
    float v0 = fmaxf(v.x + bb.x, 0.f);
    float v1 = fmaxf(v.y + bb.y, 0.f);
    float v2 = fmaxf(v.z + bb.z, 0.f);
    float v3 = fmaxf(v.w + bb.w, 0.f);

    float4 wl = *reinterpret_cast<const float4*>(&Wl[ql * 4]);
    float p = v0 * wl.x + v1 * wl.y + v2 * wl.z + v3 * wl.w;
#pragma unroll
    for (int o = 4; o; o >>= 1) p += __shfl_xor_sync(0xffffffffu, p, o);
    if (ql == 0) out[node] = p + bl[0];
}

// ---------------------------------------------------------------------------
extern "C" void kernel_launch(void* const* d_in, const int* in_sizes, int n_in,
                              void* d_out, int out_size)
{
    const float* x   = (const float*)d_in[0];
    const int*  eidx = (const int*)d_in[1];     // [2, E]
    const float* W1  = (const float*)d_in[2];
    const float* as1 = (const float*)d_in[3];
    const float* ad1 = (const float*)d_in[4];
    const float* b1  = (const float*)d_in[5];
    const float* W2  = (const float*)d_in[6];
    const float* as2 = (const float*)d_in[7];
    const float* ad2 = (const float*)d_in[8];
    const float* b2  = (const float*)d_in[9];
    const float* Wl  = (const float*)d_in[10];
    const float* bl  = (const float*)d_in[11];
    float*       out = (float*)d_out;

    const int4* src4 = (const int4*)eidx;
    const int4* dst4 = (const int4*)(eidx + N_EDGES);

    void* degKPtr = nullptr;
    cudaGetSymbolAddress(&degKPtr, g_degK);
    cudaMemsetAsync(degKPtr, 0, 4 * N_NODES * sizeof(int));

    k_precomp<<<1, 32>>>(W2, as2, ad2);
    k_p1<<<NODE_BLOCKS + EDGE4_BLOCKS, 256>>>(x, W1, as1, ad1, src4, dst4);
    k_g1t2<<<GATHER_BLOCKS, 256>>>(W2, b1);
    k_gather2<<<GATHER_BLOCKS, 256>>>(b2, Wl, bl, out);
}